// round 12
// baseline (speedup 1.0000x reference)
#include <cuda_runtime.h>
#include <cstdint>

#define CRF_B 256
#define CRF_T 512
#define CRF_L 64

// ---- bf16x2 helpers ----
__device__ __forceinline__ unsigned bfma2(unsigned a, unsigned b, unsigned c) {
    unsigned d; asm("fma.rn.bf16x2 %0, %1, %2, %3;" : "=r"(d) : "r"(a), "r"(b), "r"(c)); return d;
}
// pack (lo, hi) floats -> bf16x2 (PTX: first source goes to the HIGH half)
__device__ __forceinline__ unsigned f2bf2(float lo, float hi) {
    unsigned d; asm("cvt.rn.bf16x2.f32 %0, %1, %2;" : "=r"(d) : "f"(hi), "f"(lo)); return d;
}
__device__ __forceinline__ float bf_lo(unsigned u) { return __uint_as_float(u << 16); }
__device__ __forceinline__ float bf_hi(unsigned u) { return __uint_as_float(u & 0xffff0000u); }

// 64 CTAs, 4 batch rows per CTA, 8 warps:
//   wid 0: fwd rows {0,1} (SMSP0)   wid 1: bwd rows {0,1} (SMSP1)
//   wid 2: fwd rows {2,3} (SMSP2)   wid 3: bwd rows {2,3} (SMSP3)
//   wid 4-7: scores, one full row each.
// Each heavy warp software-pipelines TWO independent chains sharing one E
// register set: per iteration both chains' MAC streams issue back-to-back
// (ILP hides the STS->LDS exchange latency of each), one __syncwarp per
// 2 logical steps. bf16 duplicated-state layout as R11; exact power-of-2
// renorm every 4 steps per chain. Buffer of time t = buf t&1.
__global__ __launch_bounds__(256, 1)
void CRF_48266842472844_kernel(const float* __restrict__ y_true,
                               const float* __restrict__ y_pred,
                               const float* __restrict__ trans,
                               float* __restrict__ out) {
    const int tid  = threadIdx.x;
    const int lane = tid & 31;
    const int wid  = tid >> 5;

    __shared__ __align__(16) unsigned qf[2][2][2][CRF_L];  // [pair][chain][buf][word]
    __shared__ __align__(16) unsigned qb[2][2][2][CRF_L];
    __shared__ __align__(16) float2 bout2[4][32];          // beta_255 per local row
    __shared__ int   labs[4][CRF_T];
    __shared__ float sMb[4], sP[4], sTs[4];

    // chain states, live across the final barrier (fwd warps)
    float v0A = 0.f, v0B = 0.f, v1A = 0.f, v1B = 0.f, M0 = 0.f, M1 = 0.f;

// One chain's matvec (no syncwarp): reads 64 duplicated bf16x2 words,
// updates VA/VB/MM, writes words 2l,2l+1 as one STS.64.
#define CORE1(qread, qwrite, E, eX, eY, VA, VB, MM, CONSUME) do {             \
    float gA = __expf(eX), gB = __expf(eY);                                   \
    const uint4* q4 = (const uint4*)(qread);                                  \
    uint4 qv0 = q4[0];                                                        \
    if (CONSUME) {                                                            \
        unsigned eb = (qv0.x >> 7) & 0xffu;                                   \
        float r = __uint_as_float((254u - eb) << 23);   /* 2^-ef exact */     \
        MM = fmaf((float)((int)eb - 127), 0.69314718056f, MM);                \
        gA *= r; gB *= r;                                                     \
    }                                                                         \
    unsigned a0 = 0u, a1 = 0u, a2 = 0u, a3 = 0u;                              \
    _Pragma("unroll")                                                         \
    for (int m = 0; m < 16; m++) {                                            \
        uint4 qv = (m == 0) ? qv0 : q4[m];                                    \
        a0 = bfma2(qv.x, E[4 * m + 0], a0);                                   \
        a1 = bfma2(qv.y, E[4 * m + 1], a1);                                   \
        a2 = bfma2(qv.z, E[4 * m + 2], a2);                                   \
        a3 = bfma2(qv.w, E[4 * m + 3], a3);                                   \
    }                                                                         \
    float sA = (bf_lo(a0) + bf_lo(a1)) + (bf_lo(a2) + bf_lo(a3));             \
    float sB = (bf_hi(a0) + bf_hi(a1)) + (bf_hi(a2) + bf_hi(a3));             \
    VA = sA * gA; VB = sB * gB;                                               \
    ((uint2*)(qwrite))[lane] = make_uint2(f2bf2(VA, VA), f2bf2(VB, VB));      \
} while (0)

    if (wid < 4) {
        const int pair = wid >> 1;          // 0: rows {0,1}, 1: rows {2,3}
        const int kind = wid & 1;           // 0 = fwd, 1 = bwd
        const int b0   = 4 * blockIdx.x + 2 * pair;
        const float2* yp0 = (const float2*)(y_pred + (size_t)(b0)     * CRF_T * CRF_L);
        const float2* yp1 = (const float2*)(y_pred + (size_t)(b0 + 1) * CRF_T * CRF_L);
        unsigned E[64];
        float2 pe0[4], pe1[4];               // per-chain emission rings, slot = t&3

        if (kind == 0) {
            // ===== FORWARD, both chains. E[i] = bf16x2(exp(trans[i][2l]), exp(trans[i][2l+1]))
#pragma unroll
            for (int i = 0; i < 64; i++) {
                float2 r0 = __ldg((const float2*)&trans[i * CRF_L + 2 * lane]);
                E[i] = f2bf2(__expf(r0.x), __expf(r0.y));
            }
            {
                float2 e0 = yp0[lane], e1 = yp1[lane];
                v0A = __expf(e0.x); v0B = __expf(e0.y);
                v1A = __expf(e1.x); v1B = __expf(e1.y);
                ((uint2*)qf[pair][0][0])[lane] = make_uint2(f2bf2(v0A, v0A), f2bf2(v0B, v0B));
                ((uint2*)qf[pair][1][0])[lane] = make_uint2(f2bf2(v1A, v1A), f2bf2(v1B, v1B));
            }
#pragma unroll
            for (int s = 1; s <= 4; s++) {
                pe0[s & 3] = yp0[s * 32 + lane];
                pe1[s & 3] = yp1[s * 32 + lane];
            }
            const float2* pf0 = yp0 + 5 * 32 + lane;
            const float2* pf1 = yp1 + 5 * 32 + lane;
            __syncwarp();

#define FSTEP2(t_, OFF, CONSUME) do {                                         \
    float2 _e0 = pe0[(t_) & 3], _e1 = pe1[(t_) & 3];                          \
    pe0[(t_) & 3] = pf0[(OFF) * 32];                                          \
    pe1[(t_) & 3] = pf1[(OFF) * 32];                                          \
    CORE1(qf[pair][0][(t_ + 1) & 1], qf[pair][0][(t_) & 1], E,                \
          _e0.x, _e0.y, v0A, v0B, M0, CONSUME);                               \
    CORE1(qf[pair][1][(t_ + 1) & 1], qf[pair][1][(t_) & 1], E,                \
          _e1.x, _e1.y, v1A, v1B, M1, CONSUME);                               \
    __syncwarp();                                                             \
} while (0)

            FSTEP2(1, 0, false); FSTEP2(2, 1, false); FSTEP2(3, 2, false);
            pf0 += 3 * 32; pf1 += 3 * 32;
#pragma unroll 1
            for (int g4 = 0; g4 < 63; g4++) {
                const int t4 = 4 * g4 + 4;
                FSTEP2(t4 + 0, 0, true);
                FSTEP2(t4 + 1, 1, false);
                FSTEP2(t4 + 2, 2, false);
                FSTEP2(t4 + 3, 3, false);
                pf0 += 4 * 32; pf1 += 4 * 32;
            }
#undef FSTEP2
            // v0*,v1* = alpha~_255 pairs ; M0,M1 = forward norms
        } else {
            // ===== BACKWARD, both chains. E[k] = bf16x2(exp(trans[2l][k]), exp(trans[2l+1][k]))
#pragma unroll
            for (int m = 0; m < 16; m++) {
                float4 ra = __ldg((const float4*)&trans[(2 * lane)     * CRF_L + 4 * m]);
                float4 rb = __ldg((const float4*)&trans[(2 * lane + 1) * CRF_L + 4 * m]);
                E[4 * m + 0] = f2bf2(__expf(ra.x), __expf(rb.x));
                E[4 * m + 1] = f2bf2(__expf(ra.y), __expf(rb.y));
                E[4 * m + 2] = f2bf2(__expf(ra.z), __expf(rb.z));
                E[4 * m + 3] = f2bf2(__expf(ra.w), __expf(rb.w));
            }
            {
                float2 e0 = yp0[511 * 32 + lane], e1 = yp1[511 * 32 + lane];
                v0A = __expf(e0.x); v0B = __expf(e0.y);
                v1A = __expf(e1.x); v1B = __expf(e1.y);
                ((uint2*)qb[pair][0][1])[lane] = make_uint2(f2bf2(v0A, v0A), f2bf2(v0B, v0B));
                ((uint2*)qb[pair][1][1])[lane] = make_uint2(f2bf2(v1A, v1A), f2bf2(v1B, v1B));
            }
#pragma unroll
            for (int s = 510; s >= 507; s--) {
                pe0[s & 3] = yp0[s * 32 + lane];
                pe1[s & 3] = yp1[s * 32 + lane];
            }
            const float2* pf0 = yp0 + 506 * 32 + lane;
            const float2* pf1 = yp1 + 506 * 32 + lane;
            __syncwarp();

#define BSTEP2(t_, OFF, CONSUME) do {                                         \
    float2 _e0 = pe0[(t_) & 3], _e1 = pe1[(t_) & 3];                          \
    pe0[(t_) & 3] = pf0[-(OFF) * 32];                                         \
    pe1[(t_) & 3] = pf1[-(OFF) * 32];                                         \
    CORE1(qb[pair][0][(t_ + 1) & 1], qb[pair][0][(t_) & 1], E,                \
          _e0.x, _e0.y, v0A, v0B, M0, CONSUME);                               \
    CORE1(qb[pair][1][(t_ + 1) & 1], qb[pair][1][(t_) & 1], E,                \
          _e1.x, _e1.y, v1A, v1B, M1, CONSUME);                               \
    __syncwarp();                                                             \
} while (0)

            BSTEP2(510, 0, false); BSTEP2(509, 1, false); BSTEP2(508, 2, false);
            pf0 -= 3 * 32; pf1 -= 3 * 32;
#pragma unroll 1
            for (int g4 = 0; g4 < 63; g4++) {
                const int tg = 507 - 4 * g4;
                BSTEP2(tg - 0, 0, true);
                BSTEP2(tg - 1, 1, false);
                BSTEP2(tg - 2, 2, false);
                BSTEP2(tg - 3, 3, false);
                pf0 -= 4 * 32; pf1 -= 4 * 32;
            }
#undef BSTEP2
            // final: beta_255 = E u_256 per chain (renorm, no emission); u_256 in buf 0.
#pragma unroll
            for (int c = 0; c < 2; c++) {
                const uint4* q4 = (const uint4*)qb[pair][c][0];
                uint4 qv0 = q4[0];
                unsigned eb = (qv0.x >> 7) & 0xffu;
                float r = __uint_as_float((254u - eb) << 23);
                float Mf = fmaf((float)((int)eb - 127), 0.69314718056f,
                                (c == 0) ? M0 : M1);
                unsigned a0 = 0u, a1 = 0u, a2 = 0u, a3 = 0u;
#pragma unroll
                for (int m = 0; m < 16; m++) {
                    uint4 qv = (m == 0) ? qv0 : q4[m];
                    a0 = bfma2(qv.x, E[4 * m + 0], a0);
                    a1 = bfma2(qv.y, E[4 * m + 1], a1);
                    a2 = bfma2(qv.z, E[4 * m + 2], a2);
                    a3 = bfma2(qv.w, E[4 * m + 3], a3);
                }
                float oA = ((bf_lo(a0) + bf_lo(a1)) + (bf_lo(a2) + bf_lo(a3))) * r;
                float oB = ((bf_hi(a0) + bf_hi(a1)) + (bf_hi(a2) + bf_hi(a3))) * r;
                bout2[2 * pair + c][lane] = make_float2(oA, oB);
                if (lane == 0) sMb[2 * pair + c] = Mf;
            }
        }
    } else {
        // ================= SCORES (wid 4-7): one full row each ============
        const int lr = wid - 4;              // local row 0..3
        const int b  = 4 * blockIdx.x + lr;
        const float* yp = y_pred + (size_t)b * CRF_T * CRF_L;
        const float* yt = y_true + (size_t)b * CRF_T * CRF_L;
        const float4* yp4 = (const float4*)yp;
        const float4* yt4 = (const float4*)yt;
        const int hh = lane >> 4, l4 = lane & 15;

        float pacc = 0.0f;
#pragma unroll 4
        for (int t = 0; t < CRF_T; t += 2) {
            const int tt = t + hh;
            float4 p = yp4[tt * 16 + l4];
            float4 q = yt4[tt * 16 + l4];
            pacc += p.x * q.x + p.y * q.y + p.z * q.z + p.w * q.w;
            int c = -1;
            if      (q.x > 0.5f) c = 0;
            else if (q.y > 0.5f) c = 1;
            else if (q.z > 0.5f) c = 2;
            else if (q.w > 0.5f) c = 3;
            unsigned m  = __ballot_sync(0xffffffffu, c >= 0);
            unsigned mh = (m >> (hh * 16)) & 0xffffu;
            int src = hh * 16 + (__ffs(mh) - 1);
            int lab = __shfl_sync(0xffffffffu, 4 * l4 + c, src);
            if (l4 == 0) labs[lr][tt] = lab;
        }
        __syncwarp();                         // labels visible within warp

        float ts = 0.0f;
#pragma unroll 4
        for (int t0 = lane; t0 < CRF_T - 1; t0 += 32)
            ts += __ldg(&trans[labs[lr][t0] * CRF_L + labs[lr][t0 + 1]]);
#pragma unroll
        for (int s = 16; s > 0; s >>= 1) {
            pacc += __shfl_xor_sync(0xffffffffu, pacc, s);
            ts   += __shfl_xor_sync(0xffffffffu, ts, s);
        }
        if (lane == 0) { sP[lr] = pacc; sTs[lr] = ts; }
    }

    __syncthreads();

    // ================= COMBINE: fwd warps (wid 0, 2) =====================
    if (wid < 4 && (wid & 1) == 0) {
        const int pair = wid >> 1;
        float2 b0 = bout2[2 * pair + 0][lane];
        float2 b1 = bout2[2 * pair + 1][lane];
        float d0 = v0A * b0.x + v0B * b0.y;
        float d1 = v1A * b1.x + v1B * b1.y;
#pragma unroll
        for (int s = 16; s > 0; s >>= 1) {
            d0 += __shfl_xor_sync(0xffffffffu, d0, s);
            d1 += __shfl_xor_sync(0xffffffffu, d1, s);
        }
        if (lane == 0) {
            int lr0 = 2 * pair, lr1 = 2 * pair + 1;
            out[4 * blockIdx.x + lr0] = (M0 + sMb[lr0] + logf(d0)) - sP[lr0] - sTs[lr0];
            out[4 * blockIdx.x + lr1] = (M1 + sMb[lr1] + logf(d1)) - sP[lr1] - sTs[lr1];
        }
    }
#undef CORE1
}

extern "C" void kernel_launch(void* const* d_in, const int* in_sizes, int n_in,
                              void* d_out, int out_size) {
    const float* y_true = (const float*)d_in[0];
    const float* y_pred = (const float*)d_in[1];
    const float* trans  = (const float*)d_in[2];
    float* out = (float*)d_out;
    (void)in_sizes; (void)n_in; (void)out_size;
    CRF_48266842472844_kernel<<<CRF_B / 4, 256>>>(y_true, y_pred, trans, out);
}

// round 13
// speedup vs baseline: 1.8331x; 1.8331x over previous
#include <cuda_runtime.h>
#include <cstdint>

#define CRF_B 256
#define CRF_T 512
#define CRF_L 64

// ---- bf16x2 helpers ----
__device__ __forceinline__ unsigned bfma2(unsigned a, unsigned b, unsigned c) {
    unsigned d; asm("fma.rn.bf16x2 %0, %1, %2, %3;" : "=r"(d) : "r"(a), "r"(b), "r"(c)); return d;
}
// pack (lo, hi) -> bf16x2 (PTX cvt: FIRST source lands in the HIGH half)
__device__ __forceinline__ unsigned f2bf2(float lo, float hi) {
    unsigned d; asm("cvt.rn.bf16x2.f32 %0, %1, %2;" : "=r"(d) : "f"(hi), "f"(lo)); return d;
}
__device__ __forceinline__ float bf_lo(unsigned u) { return __uint_as_float(u << 16); }
__device__ __forceinline__ float bf_hi(unsigned u) { return __uint_as_float(u & 0xffff0000u); }

// 128 CTAs (1/SM), 2 batch rows per CTA, 12 warps:
//   Chains: 0 = fwd row0, 1 = bwd row0, 2 = fwd row1, 3 = bwd row1.
//   Heavy warps wid 0-7: chain = wid>>1, half = wid&1; lane owns ONE label
//   jj = half*32+lane. SMSP = wid%4 -> each SMSP hosts halves of TWO
//   DIFFERENT chains (barrier waits of one overlap issue of the other).
//   wid 8-11: score warps (row = sw>>1, t-half = sw&1), as R11.
// State: 64 bf16 in natural order (no duplication); per step each warp does
// 8 LDS.128 + 32 HFMA2 (bf16x2 packed over i-pairs) + 1 STS.U16, then
// bar.sync(1+chain, 64). bar.sync drains STS (HW-native). Renorm every 4
// steps by exact power-of-2 from stale w[0] bf16 exponent.
// Buffer of time t = buf t&1 (fwd init buf0; bwd u_511 init buf1).
__global__ __launch_bounds__(384, 1)
void CRF_48266842472844_kernel(const float* __restrict__ y_true,
                               const float* __restrict__ y_pred,
                               const float* __restrict__ trans,
                               float* __restrict__ out) {
    const int tid  = threadIdx.x;
    const int lane = tid & 31;
    const int wid  = tid >> 5;

    __shared__ __align__(16) unsigned short qs[4][2][CRF_L];  // [chain][buf][label]
    __shared__ __align__(16) float boutf[2][CRF_L];           // beta_255 per row
    __shared__ int   labs[2][CRF_T];
    __shared__ float sMf[2], sMb[2], sDot[2][2], sP[2][2], sTs[2][2];

    float V = 0.0f, M = 0.0f;   // live across final barriers (heavy warps)

    if (wid < 8) {
        const int chain = wid >> 1;       // 0 fwdR0, 1 bwdR0, 2 fwdR1, 3 bwdR1
        const int half  = wid & 1;
        const int row   = chain >> 1;
        const int kind  = chain & 1;      // 0 = fwd, 1 = bwd
        const int jj    = half * 32 + lane;
        const int barid = 1 + chain;      // named barriers 1..4
        const int b     = 2 * blockIdx.x + row;
        const float* yp = y_pred + (size_t)b * CRF_T * CRF_L;
        unsigned E[32];                   // E[k] = bf16x2 over i-pair (2k,2k+1)
        float pe[4];                      // emission ring, slot = t & 3

// One matvec step for this warp's 32 outputs (labels jj):
//  s(jj) = sum_k wpair_k .* Epair_k  (bf16x2), reduced lo+hi in fp32.
#define STEP1(t_, eIn, CONSUME) do {                                          \
    float g = __expf(eIn);                                                    \
    const uint4* q4 = (const uint4*)qs[chain][((t_) + 1) & 1];                \
    uint4 qv0 = q4[0];                                                        \
    if (CONSUME) {                                                            \
        unsigned eb = (qv0.x >> 7) & 0xffu;       /* bf16 exp of w[0] */      \
        float r = __uint_as_float((254u - eb) << 23);   /* 2^-ef exact */     \
        M = fmaf((float)((int)eb - 127), 0.69314718056f, M);                  \
        g *= r;                                                               \
    }                                                                         \
    unsigned a0 = 0u, a1 = 0u;                                                \
    _Pragma("unroll")                                                         \
    for (int m = 0; m < 8; m++) {                                             \
        uint4 qv = (m == 0) ? qv0 : q4[m];                                    \
        a0 = bfma2(qv.x, E[4 * m + 0], a0);                                   \
        a1 = bfma2(qv.y, E[4 * m + 1], a1);                                   \
        a0 = bfma2(qv.z, E[4 * m + 2], a0);                                   \
        a1 = bfma2(qv.w, E[4 * m + 3], a1);                                   \
    }                                                                         \
    float s = (bf_lo(a0) + bf_hi(a0)) + (bf_lo(a1) + bf_hi(a1));              \
    V = s * g;                                                                \
    qs[chain][(t_) & 1][jj] = (unsigned short)f2bf2(V, V);                    \
    asm volatile("bar.sync %0, 64;" :: "r"(barid) : "memory");                \
} while (0)

        if (kind == 0) {
            // ===== FORWARD alpha, t = 0..255. Column jj of E.
#pragma unroll
            for (int k = 0; k < 32; k++) {
                float e0 = __expf(__ldg(&trans[(2 * k)     * CRF_L + jj]));
                float e1 = __expf(__ldg(&trans[(2 * k + 1) * CRF_L + jj]));
                E[k] = f2bf2(e0, e1);
            }
            V = __expf(yp[jj]);
            qs[chain][0][jj] = (unsigned short)f2bf2(V, V);   // alpha_0 -> buf 0
            pe[1] = yp[1 * CRF_L + jj];
            pe[2] = yp[2 * CRF_L + jj];
            pe[3] = yp[3 * CRF_L + jj];
            pe[0] = yp[4 * CRF_L + jj];
            const float* pf = yp + 5 * CRF_L + jj;    // next prefetch: t=5
            asm volatile("bar.sync %0, 64;" :: "r"(barid) : "memory");

#define FSTEP(t_, OFF, CONSUME) do {                                          \
    float _e = pe[(t_) & 3];                                                  \
    pe[(t_) & 3] = pf[(OFF) * CRF_L];                                         \
    STEP1(t_, _e, CONSUME);                                                   \
} while (0)

            FSTEP(1, 0, false); FSTEP(2, 1, false); FSTEP(3, 2, false);
            pf += 3 * CRF_L;
#pragma unroll 1
            for (int g4 = 0; g4 < 63; g4++) {
                const int t4 = 4 * g4 + 4;
                FSTEP(t4 + 0, 0, true);
                FSTEP(t4 + 1, 1, false);
                FSTEP(t4 + 2, 2, false);
                FSTEP(t4 + 3, 3, false);
                pf += 4 * CRF_L;
            }
#undef FSTEP
            // V = alpha~_255(jj), M = forward norm
        } else {
            // ===== BACKWARD u_t = g_t o (E u_{t+1}), t = 510..256. Row jj of E.
#pragma unroll
            for (int m = 0; m < 16; m++) {
                float4 ra = __ldg((const float4*)&trans[jj * CRF_L + 4 * m]);
                E[2 * m]     = f2bf2(__expf(ra.x), __expf(ra.y));
                E[2 * m + 1] = f2bf2(__expf(ra.z), __expf(ra.w));
            }
            V = __expf(yp[511 * CRF_L + jj]);                 // u_511 = g_511
            qs[chain][1][jj] = (unsigned short)f2bf2(V, V);   // -> buf 1 (511&1)
            pe[2] = yp[510 * CRF_L + jj];
            pe[1] = yp[509 * CRF_L + jj];
            pe[0] = yp[508 * CRF_L + jj];
            pe[3] = yp[507 * CRF_L + jj];
            const float* pf = yp + 506 * CRF_L + jj;  // next prefetch: t=506
            asm volatile("bar.sync %0, 64;" :: "r"(barid) : "memory");

#define BSTEP(t_, OFF, CONSUME) do {                                          \
    float _e = pe[(t_) & 3];                                                  \
    pe[(t_) & 3] = pf[-(OFF) * CRF_L];                                        \
    STEP1(t_, _e, CONSUME);                                                   \
} while (0)

            BSTEP(510, 0, false); BSTEP(509, 1, false); BSTEP(508, 2, false);
            pf -= 3 * CRF_L;
#pragma unroll 1
            for (int g4 = 0; g4 < 63; g4++) {
                const int tg = 507 - 4 * g4;
                BSTEP(tg - 0, 0, true);
                BSTEP(tg - 1, 1, false);
                BSTEP(tg - 2, 2, false);
                BSTEP(tg - 3, 3, false);
                pf -= 4 * CRF_L;
            }
#undef BSTEP
            // final: beta_255 = E u_256 (renorm, no emission). u_256 in buf 0.
            {
                const uint4* q4 = (const uint4*)qs[chain][0];
                uint4 qv0 = q4[0];
                unsigned eb = (qv0.x >> 7) & 0xffu;
                float r = __uint_as_float((254u - eb) << 23);
                M = fmaf((float)((int)eb - 127), 0.69314718056f, M);
                unsigned a0 = 0u, a1 = 0u;
#pragma unroll
                for (int m = 0; m < 8; m++) {
                    uint4 qv = (m == 0) ? qv0 : q4[m];
                    a0 = bfma2(qv.x, E[4 * m + 0], a0);
                    a1 = bfma2(qv.y, E[4 * m + 1], a1);
                    a0 = bfma2(qv.z, E[4 * m + 2], a0);
                    a1 = bfma2(qv.w, E[4 * m + 3], a1);
                }
                float s = (bf_lo(a0) + bf_hi(a0)) + (bf_lo(a1) + bf_hi(a1));
                boutf[row][jj] = s * r;
                if (half == 0 && lane == 0) sMb[row] = M;
            }
        }
#undef STEP1
    } else {
        // ================= SCORES (wid 8-11) =============================
        const int sw     = wid - 8;
        const int row    = sw >> 1;
        const int half_t = sw & 1;
        const int b      = 2 * blockIdx.x + row;
        const float* yp = y_pred + (size_t)b * CRF_T * CRF_L;
        const float* yt = y_true + (size_t)b * CRF_T * CRF_L;
        const float4* yp4 = (const float4*)yp;
        const float4* yt4 = (const float4*)yt;
        const int base = half_t * 256;
        const int hh = lane >> 4, l4 = lane & 15;

        float pacc = 0.0f;
#pragma unroll 4
        for (int t = base; t < base + 256; t += 2) {
            const int tt = t + hh;
            float4 p = yp4[tt * 16 + l4];
            float4 q = yt4[tt * 16 + l4];
            pacc += p.x * q.x + p.y * q.y + p.z * q.z + p.w * q.w;
            int c = -1;
            if      (q.x > 0.5f) c = 0;
            else if (q.y > 0.5f) c = 1;
            else if (q.z > 0.5f) c = 2;
            else if (q.w > 0.5f) c = 3;
            unsigned m  = __ballot_sync(0xffffffffu, c >= 0);
            unsigned mh = (m >> (hh * 16)) & 0xffffu;
            int src = hh * 16 + (__ffs(mh) - 1);
            int lab = __shfl_sync(0xffffffffu, 4 * l4 + c, src);
            if (l4 == 0) labs[row][tt] = lab;
        }
        asm volatile("bar.sync 5, 128;" ::: "memory");   // stitch labels (wid 8-11)

        float ts = 0.0f;
        const int tmax = half_t ? (CRF_T - 1) : 256;
#pragma unroll 4
        for (int t0 = base + lane; t0 < tmax; t0 += 32)
            ts += __ldg(&trans[labs[row][t0] * CRF_L + labs[row][t0 + 1]]);
#pragma unroll
        for (int s = 16; s > 0; s >>= 1) {
            pacc += __shfl_xor_sync(0xffffffffu, pacc, s);
            ts   += __shfl_xor_sync(0xffffffffu, ts, s);
        }
        if (lane == 0) { sP[row][half_t] = pacc; sTs[row][half_t] = ts; }
    }

    __syncthreads();

    // ====== partial dots: fwd warps (chains 0, 2) ========================
    if (wid < 8 && ((wid >> 1) & 1) == 0) {
        const int chain = wid >> 1, half = wid & 1, row = chain >> 1;
        const int jj = half * 32 + lane;
        float d = V * boutf[row][jj];
#pragma unroll
        for (int s = 16; s > 0; s >>= 1)
            d += __shfl_xor_sync(0xffffffffu, d, s);
        if (lane == 0) {
            sDot[row][half] = d;
            if (half == 0) sMf[row] = M;
        }
    }
    __syncthreads();

    if (tid < 2) {
        const int row = tid;
        float Z = sMf[row] + sMb[row] + logf(sDot[row][0] + sDot[row][1]);
        out[2 * blockIdx.x + row] =
            Z - (sP[row][0] + sP[row][1]) - (sTs[row][0] + sTs[row][1]);
    }
}

extern "C" void kernel_launch(void* const* d_in, const int* in_sizes, int n_in,
                              void* d_out, int out_size) {
    const float* y_true = (const float*)d_in[0];
    const float* y_pred = (const float*)d_in[1];
    const float* trans  = (const float*)d_in[2];
    float* out = (float*)d_out;
    (void)in_sizes; (void)n_in; (void)out_size;
    CRF_48266842472844_kernel<<<CRF_B / 2, 384>>>(y_true, y_pred, trans, out);
}